// round 11
// baseline (speedup 1.0000x reference)
#include <cuda_runtime.h>
#include <stdint.h>

// Problem constants (fixed by the dataset)
#define NUM_RELS   64
#define NUM_BASES  16
#define IN_F       128
#define OUT_F      128
#define N_CAP      100352          // 98*1024 >= n_nodes (100000)
#define E_CAP      1048576         // NUM_RELS * 16384
#define SCAN_BLKS  98              // N_CAP / 1024

#define ASTR 132                   // A-tile smem stride (floats)
#define WSTR 136                   // W-tile smem stride (floats)

// Scratch (static device globals; no allocations)
__device__ float g_W[NUM_RELS * IN_F * OUT_F];   // per-relation weights, tf32-rounded
__device__ float g_featT[(size_t)N_CAP * IN_F];  // feat, tf32-rounded
__device__ float g_msg[(size_t)E_CAP * OUT_F];   // dst-sorted messages (512 MB)
__device__ int   g_cnt[N_CAP];                   // per-dst edge counts
__device__ int   g_offp[N_CAP];                  // block-local exclusive prefix
__device__ int   g_off[N_CAP + 1];               // CSR offsets
__device__ int   g_cur[N_CAP];                   // running cursor for perm
__device__ int   g_bsum[SCAN_BLKS];
__device__ int   g_bbase[SCAN_BLKS];
__device__ int   g_perm[E_CAP];                  // dst-sorted rank of each edge
__device__ int   g_src64;
__device__ int   g_dst64;

// ---------------------------------------------------------------------------
// helpers
// ---------------------------------------------------------------------------
__device__ __forceinline__ float f2tf(float f) {
    unsigned u;
    asm("cvt.rna.tf32.f32 %0, %1;" : "=r"(u) : "f"(f));
    return __uint_as_float(u);
}

__device__ __forceinline__ void mma8(float d[4], unsigned a0, unsigned a1,
                                     unsigned a2, unsigned a3,
                                     unsigned b0, unsigned b1) {
    asm("mma.sync.aligned.m16n8k8.row.col.f32.tf32.tf32.f32 "
        "{%0,%1,%2,%3},{%4,%5,%6,%7},{%8,%9},{%0,%1,%2,%3};"
        : "+f"(d[0]), "+f"(d[1]), "+f"(d[2]), "+f"(d[3])
        : "r"(a0), "r"(a1), "r"(a2), "r"(a3), "r"(b0), "r"(b1));
}

#define CP_COMMIT() asm volatile("cp.async.commit_group;" ::: "memory")
#define CP_WAIT(N)  asm volatile("cp.async.wait_group %0;" :: "n"(N) : "memory")

// Single extern-shared symbol for the whole TU
extern __shared__ char smem_c[];

__device__ __forceinline__ long edge_dst(const void* dstv, int d64, long e) {
    return d64 ? (long)((const long long*)dstv)[e] : (long)((const int*)dstv)[e];
}

// Warp-tile mainloop: 32x64 output per warp (8 warps), K=128 in 16 k8 slices.
__device__ __forceinline__ void mma_tile(const float* As, const float* Ws,
                                         int warp, int lane, float acc[2][8][4]) {
    const int gid = lane >> 2, ctg = lane & 3;
    const int wm = warp & 3, wn = warp >> 2;
    const unsigned* Ab = (const unsigned*)As + (wm * 32 + gid) * ASTR + ctg;
    const unsigned* Bb = (const unsigned*)Ws + ctg * WSTR + wn * 64 + gid;
    #pragma unroll
    for (int ks = 0; ks < 16; ks++) {
        unsigned a[2][4], b[8][2];
        #pragma unroll
        for (int mb = 0; mb < 2; mb++) {
            const unsigned* p = Ab + mb * 16 * ASTR + ks * 8;
            a[mb][0] = p[0];
            a[mb][1] = p[8 * ASTR];
            a[mb][2] = p[4];
            a[mb][3] = p[8 * ASTR + 4];
        }
        #pragma unroll
        for (int nt = 0; nt < 8; nt++) {
            const unsigned* p = Bb + ks * 8 * WSTR + nt * 8;
            b[nt][0] = p[0];
            b[nt][1] = p[4 * WSTR];
        }
        #pragma unroll
        for (int mb = 0; mb < 2; mb++)
            #pragma unroll
            for (int nt = 0; nt < 8; nt++)
                mma8(acc[mb][nt], a[mb][0], a[mb][1], a[mb][2], a[mb][3],
                     b[nt][0], b[nt][1]);
    }
}

// ---------------------------------------------------------------------------
// K0: basis composition (tf32) + index-width detection
// ---------------------------------------------------------------------------
__global__ void basis_kernel(const float* __restrict__ weight,
                             const float* __restrict__ w_comp,
                             const void* __restrict__ srcv,
                             const void* __restrict__ dstv) {
    if (blockIdx.x == 0 && threadIdx.x == 0) {
        const unsigned* s = (const unsigned*)srcv;
        const unsigned* d = (const unsigned*)dstv;
        int s64 = 1, d64 = 1;
        #pragma unroll
        for (int i = 1; i < 32; i += 2) {
            if (s[i] != 0u) s64 = 0;
            if (d[i] != 0u) d64 = 0;
        }
        g_src64 = s64;
        g_dst64 = d64;
    }
    int gid = blockIdx.x * blockDim.x + threadIdx.x;
    if (gid < NUM_RELS * IN_F * OUT_F) {
        int r = gid >> 14;
        int ko = gid & 16383;
        float acc = 0.0f;
        #pragma unroll
        for (int b = 0; b < NUM_BASES; b++)
            acc = fmaf(__ldg(&w_comp[r * NUM_BASES + b]),
                       __ldg(&weight[(b << 14) + ko]), acc);
        g_W[gid] = f2tf(acc);
    }
}

// ---------------------------------------------------------------------------
// K0b: round feat to tf32 into g_featT
// ---------------------------------------------------------------------------
__global__ void round_feat_kernel(const float* __restrict__ feat, int n4) {
    int i = blockIdx.x * blockDim.x + threadIdx.x;
    if (i < n4) {
        float4 v = ((const float4*)feat)[i];
        v.x = f2tf(v.x); v.y = f2tf(v.y); v.z = f2tf(v.z); v.w = f2tf(v.w);
        ((float4*)g_featT)[i] = v;
    }
}

// ---------------------------------------------------------------------------
// Sort kernels: zero -> hist -> scan1 -> scan2 -> scan3 -> perm
// ---------------------------------------------------------------------------
__global__ void zero_cnt_kernel() {
    int i = blockIdx.x * blockDim.x + threadIdx.x;
    if (i < N_CAP) g_cnt[i] = 0;
}

__global__ void hist_kernel(const void* __restrict__ dstv, int E) {
    int e = blockIdx.x * blockDim.x + threadIdx.x;
    if (e < E) {
        long d = edge_dst(dstv, g_dst64, e);
        atomicAdd(&g_cnt[d], 1);
    }
}

__global__ void scan1_kernel() {
    int* sh = (int*)smem_c;
    int tid = threadIdx.x;
    int i = blockIdx.x * 1024 + tid;
    int v = g_cnt[i];
    sh[tid] = v;
    __syncthreads();
    #pragma unroll
    for (int off = 1; off < 1024; off <<= 1) {
        int t = (tid >= off) ? sh[tid - off] : 0;
        __syncthreads();
        sh[tid] += t;
        __syncthreads();
    }
    g_offp[i] = sh[tid] - v;    // exclusive within block
    if (tid == 1023) g_bsum[blockIdx.x] = sh[tid];
}

__global__ void scan2_kernel() {
    if (threadIdx.x == 0) {
        int run = 0;
        for (int b = 0; b < SCAN_BLKS; b++) {
            g_bbase[b] = run;
            run += g_bsum[b];
        }
    }
}

__global__ void scan3_kernel(int E) {
    int i = blockIdx.x * blockDim.x + threadIdx.x;
    if (i < N_CAP) {
        int v = g_offp[i] + g_bbase[i >> 10];
        g_off[i] = v;
        g_cur[i] = v;
    }
    if (i == 0) g_off[N_CAP] = E;
}

__global__ void perm_kernel(const void* __restrict__ dstv, int E) {
    int e = blockIdx.x * blockDim.x + threadIdx.x;
    if (e < E) {
        long d = edge_dst(dstv, g_dst64, e);
        g_perm[e] = atomicAdd(&g_cur[d], 1);
    }
}

// ---------------------------------------------------------------------------
// K1: self-loop  out[n] = bias + feat[n] @ loop_weight   (tf32 MMA, 8 warps)
// ---------------------------------------------------------------------------
__global__ void __launch_bounds__(256, 1)
selfloop_mma_kernel(const float* __restrict__ lw,
                    const float* __restrict__ bias,
                    float* __restrict__ out, int n_nodes) {
    float* smem = (float*)smem_c;
    float* Ws = smem;                    // 128 * WSTR
    float* As = smem + 128 * WSTR;       // 128 * ASTR
    int tid = threadIdx.x, warp = tid >> 5, lane = tid & 31;

    const float4* Wg = (const float4*)lw;
    for (int i = tid; i < 4096; i += 256) {
        float4 v = Wg[i];
        v.x = f2tf(v.x); v.y = f2tf(v.y); v.z = f2tf(v.z); v.w = f2tf(v.w);
        int r = i >> 5, c4 = i & 31;
        ((float4*)(Ws + r * WSTR))[c4] = v;
    }

    int nodeBase = blockIdx.x * 128;
    {
        int row = tid >> 1, half = tid & 1;
        int n = nodeBase + row;
        if (n >= n_nodes) n = n_nodes - 1;
        const float4* srow = (const float4*)(g_featT + (long)n * IN_F + half * 64);
        float4* drow = (float4*)(As + row * ASTR + half * 64);
        #pragma unroll
        for (int i = 0; i < 16; i++) drow[i] = srow[i];
    }
    __syncthreads();

    float acc[2][8][4];
    #pragma unroll
    for (int mb = 0; mb < 2; mb++)
        #pragma unroll
        for (int nt = 0; nt < 8; nt++)
            #pragma unroll
            for (int q = 0; q < 4; q++) acc[mb][nt][q] = 0.0f;

    mma_tile(As, Ws, warp, lane, acc);

    const int gid = lane >> 2, ctg = lane & 3;
    const int wm = warp & 3, wn = warp >> 2;
    #pragma unroll
    for (int mb = 0; mb < 2; mb++) {
        #pragma unroll
        for (int nt = 0; nt < 8; nt++) {
            int r = wm * 32 + mb * 16 + gid;
            int c = wn * 64 + nt * 8 + 2 * ctg;
            float2 b2 = *(const float2*)(bias + c);
            int n0 = nodeBase + r;
            if (n0 < n_nodes)
                *(float2*)(out + (long)n0 * OUT_F + c) =
                    make_float2(acc[mb][nt][0] + b2.x, acc[mb][nt][1] + b2.y);
            int n1 = nodeBase + r + 8;
            if (n1 < n_nodes)
                *(float2*)(out + (long)n1 * OUT_F + c) =
                    make_float2(acc[mb][nt][2] + b2.x, acc[mb][nt][3] + b2.y);
        }
    }
}

// ---------------------------------------------------------------------------
// K2: edge grouped GEMM -> dst-sorted msg rows (streaming stores, no atomics)
// Block = 1024 edges (one relation), 8 tiles of 128, double-buffered cp.async.
// smem floats: W 0..17407 | A0 17408.. | A1 34304.. | perm 51200 | nrm 51712
// ---------------------------------------------------------------------------
#define EDGE_SMEM_FLOATS 52224

__device__ __forceinline__ void gather_tile(float* Abuf, int* perms, float* nrms,
                                            const void* srcv,
                                            const float* norm, long e0,
                                            int s64, int tid) {
    int row = tid >> 1, half = tid & 1;
    long e = e0 + row;
    long sidx = s64 ? (long)((const long long*)srcv)[e]
                    : (long)((const int*)srcv)[e];
    const float* srow = g_featT + sidx * IN_F + half * 64;
    unsigned daddr =
        (unsigned)__cvta_generic_to_shared(Abuf + row * ASTR + half * 64);
    #pragma unroll
    for (int i = 0; i < 16; i++)
        asm volatile("cp.async.cg.shared.global [%0], [%1], 16;" ::
                     "r"(daddr + i * 16), "l"(srow + i * 4));
    if (tid < 128) {
        long ee = e0 + tid;
        perms[tid] = g_perm[ee];
        nrms[tid] = norm[ee];
    }
}

__global__ void __launch_bounds__(256, 1)
edge_mma_kernel(const void* __restrict__ srcv,
                const float* __restrict__ norm,
                int section) {
    float* smem = (float*)smem_c;
    float* Ws = smem;
    float* A0 = smem + 17408;
    float* A1 = smem + 34304;
    int*   prm_s = (int*)(smem + 51200);     // [2][128]
    float* nrm_s = smem + 51712;             // [2][128]

    int tid = threadIdx.x, warp = tid >> 5, lane = tid & 31;
    long eBase = (long)blockIdx.x * 1024;
    int rel = (int)(eBase / section);

    // Prologue: W (cp.async) + gather tile0 -> buf0, one commit group.
    {
        const float* Wg = g_W + (size_t)rel * 16384;
        for (int i = tid; i < 4096; i += 256) {
            int r = i >> 5, c4 = i & 31;
            unsigned daddr = (unsigned)__cvta_generic_to_shared(
                (float4*)(Ws + r * WSTR) + c4);
            asm volatile("cp.async.cg.shared.global [%0], [%1], 16;" ::
                         "r"(daddr), "l"(Wg + i * 4));
        }
    }
    const int s64 = g_src64;
    gather_tile(A0, prm_s, nrm_s, srcv, norm, eBase, s64, tid);
    CP_COMMIT();

    const int gid = lane >> 2, ctg = lane & 3;
    const int wm = warp & 3, wn = warp >> 2;
    float* Ab[2] = {A0, A1};

    #pragma unroll 1
    for (int t = 0; t < 8; t++) {
        int b = t & 1;
        __syncthreads();   // protect buf b^1 (readers from iter t-1 done)
        if (t < 7) {
            gather_tile(Ab[b ^ 1], prm_s + (b ^ 1) * 128,
                        nrm_s + (b ^ 1) * 128, srcv, norm,
                        eBase + (long)(t + 1) * 128, s64, tid);
            CP_COMMIT();
            CP_WAIT(1);    // buf b's group complete
        } else {
            CP_WAIT(0);
        }
        __syncthreads();   // all threads' gathers for buf b visible

        float acc[2][8][4];
        #pragma unroll
        for (int mb = 0; mb < 2; mb++)
            #pragma unroll
            for (int nt = 0; nt < 8; nt++)
                #pragma unroll
                for (int q = 0; q < 4; q++) acc[mb][nt][q] = 0.0f;

        mma_tile(Ab[b], Ws, warp, lane, acc);

        // Fragment-direct epilogue: scale by norm, shfl-merge lane pairs,
        // streaming float4 stores to dst-sorted msg rows. No atomics.
        const int* myprm = prm_s + b * 128;
        const float* mynrm = nrm_s + b * 128;
        #pragma unroll
        for (int mb = 0; mb < 2; mb++) {
            int r0 = wm * 32 + mb * 16 + gid;
            int r1 = r0 + 8;
            float nv0 = mynrm[r0], nv1 = mynrm[r1];
            long p0 = myprm[r0], p1 = myprm[r1];
            #pragma unroll
            for (int nt = 0; nt < 8; nt++) {
                float x0 = acc[mb][nt][0] * nv0, x1 = acc[mb][nt][1] * nv0;
                float x2 = acc[mb][nt][2] * nv1, x3 = acc[mb][nt][3] * nv1;
                float y0 = __shfl_xor_sync(0xFFFFFFFFu, x0, 1);
                float y1 = __shfl_xor_sync(0xFFFFFFFFu, x1, 1);
                float y2 = __shfl_xor_sync(0xFFFFFFFFu, x2, 1);
                float y3 = __shfl_xor_sync(0xFFFFFFFFu, x3, 1);
                if (!(lane & 1)) {   // ctg even: owns cols 2ctg..2ctg+3
                    int c = wn * 64 + nt * 8 + 2 * ctg;
                    __stcs((float4*)(g_msg + p0 * OUT_F + c),
                           make_float4(x0, x1, y0, y1));
                    __stcs((float4*)(g_msg + p1 * OUT_F + c),
                           make_float4(x2, x3, y2, y3));
                }
            }
        }
    }
}

// ---------------------------------------------------------------------------
// K3: aggregate  out[n] = relu(out[n] + sum msg rows [off[n], off[n+1]))
// One warp per node; contiguous msg rows (dst-sorted).
// ---------------------------------------------------------------------------
__global__ void __launch_bounds__(256)
agg_kernel(float* __restrict__ out, int n_nodes) {
    int warp = threadIdx.x >> 5, lane = threadIdx.x & 31;
    int n = blockIdx.x * 8 + warp;
    if (n >= n_nodes) return;
    int s = g_off[n], e = g_off[n + 1];
    float4* orow = (float4*)(out + (long)n * OUT_F);
    float4 acc = orow[lane];
    const float4* msg4 = (const float4*)g_msg;
    for (int i = s; i < e; i++) {
        float4 m = __ldcs(msg4 + (long)i * 32 + lane);
        acc.x += m.x; acc.y += m.y; acc.z += m.z; acc.w += m.w;
    }
    acc.x = fmaxf(acc.x, 0.f);
    acc.y = fmaxf(acc.y, 0.f);
    acc.z = fmaxf(acc.z, 0.f);
    acc.w = fmaxf(acc.w, 0.f);
    orow[lane] = acc;
}

// ---------------------------------------------------------------------------
extern "C" void kernel_launch(void* const* d_in, const int* in_sizes, int n_in,
                              void* d_out, int out_size) {
    const float* feat        = (const float*)d_in[0];
    const float* weight      = (const float*)d_in[1];
    const float* w_comp      = (const float*)d_in[2];
    const float* h_bias      = (const float*)d_in[3];
    const float* loop_weight = (const float*)d_in[4];
    const float* norm        = (const float*)d_in[5];
    const void*  src         = d_in[6];
    const void*  dst         = d_in[7];

    const int E       = in_sizes[5];
    const int n_nodes = in_sizes[0] / IN_F;
    const int section = E / NUM_RELS;

    float* out = (float*)d_out;

    const int SMEM_SELF = (128 * WSTR + 128 * ASTR) * 4;   // ~134 KB
    const int SMEM_EDGE = EDGE_SMEM_FLOATS * 4;            // ~204 KB
    cudaFuncSetAttribute(selfloop_mma_kernel,
                         cudaFuncAttributeMaxDynamicSharedMemorySize, SMEM_SELF);
    cudaFuncSetAttribute(edge_mma_kernel,
                         cudaFuncAttributeMaxDynamicSharedMemorySize, SMEM_EDGE);

    // K0: basis composition + index detect (sets g_dst64 for sort kernels)
    basis_kernel<<<(NUM_RELS * IN_F * OUT_F + 255) / 256, 256>>>(weight, w_comp, src, dst);

    // K0b: round feat to tf32
    int n4 = n_nodes * (IN_F / 4);
    round_feat_kernel<<<(n4 + 255) / 256, 256>>>(feat, n4);

    // Counting sort of edges by dst -> CSR off[] + per-edge perm[]
    zero_cnt_kernel<<<(N_CAP + 255) / 256, 256>>>();
    hist_kernel<<<(E + 255) / 256, 256>>>(dst, E);
    scan1_kernel<<<SCAN_BLKS, 1024, 1024 * 4>>>();
    scan2_kernel<<<1, 32>>>();
    scan3_kernel<<<(N_CAP + 255) / 256, 256>>>(E);
    perm_kernel<<<(E + 255) / 256, 256>>>(dst, E);

    // K1: self-loop (initializes out = bias + feat @ loop_weight)
    selfloop_mma_kernel<<<(n_nodes + 127) / 128, 256, SMEM_SELF>>>(loop_weight, h_bias, out, n_nodes);

    // K2: edge grouped GEMM -> dst-sorted msg (no atomics)
    edge_mma_kernel<<<E / 1024, 256, SMEM_EDGE>>>(src, norm, section);

    // K3: aggregate + relu
    agg_kernel<<<(n_nodes + 7) / 8, 256>>>(out, n_nodes);
}

// round 13
// speedup vs baseline: 1.5703x; 1.5703x over previous
#include <cuda_runtime.h>
#include <cuda_fp16.h>
#include <stdint.h>

// Problem constants (fixed by the dataset)
#define NUM_RELS   64
#define NUM_BASES  16
#define IN_F       128
#define OUT_F      128
#define N_CAP      100352          // >= n_nodes (100000)

#define ASTR 132                   // selfloop A stride (floats)
#define WSTR 136                   // selfloop W stride (floats)

#define RSTRW 68                   // fp16 tile row stride in 32-bit words (272 B)

// Scratch (static device globals; no allocations)
__device__ float  g_featT[(size_t)N_CAP * IN_F];  // tf32-rounded feat (selfloop)
__device__ __half g_featH[(size_t)N_CAP * IN_F];  // fp16 feat (edge GEMM)
__device__ __half g_WH[NUM_RELS * OUT_F * IN_F];  // W^T fp16, [r][o][k]
__device__ int g_src64;
__device__ int g_dst64;

// ---------------------------------------------------------------------------
// helpers
// ---------------------------------------------------------------------------
__device__ __forceinline__ float f2tf(float f) {
    unsigned u;
    asm("cvt.rna.tf32.f32 %0, %1;" : "=r"(u) : "f"(f));
    return __uint_as_float(u);
}

// tf32 m16n8k8 (selfloop)
__device__ __forceinline__ void mma8(float d[4], unsigned a0, unsigned a1,
                                     unsigned a2, unsigned a3,
                                     unsigned b0, unsigned b1) {
    asm("mma.sync.aligned.m16n8k8.row.col.f32.tf32.tf32.f32 "
        "{%0,%1,%2,%3},{%4,%5,%6,%7},{%8,%9},{%0,%1,%2,%3};"
        : "+f"(d[0]), "+f"(d[1]), "+f"(d[2]), "+f"(d[3])
        : "r"(a0), "r"(a1), "r"(a2), "r"(a3), "r"(b0), "r"(b1));
}

// fp16 m16n8k16 (edge GEMM)
__device__ __forceinline__ void mma16(float d[4], unsigned a0, unsigned a1,
                                      unsigned a2, unsigned a3,
                                      unsigned b0, unsigned b1) {
    asm("mma.sync.aligned.m16n8k16.row.col.f32.f16.f16.f32 "
        "{%0,%1,%2,%3},{%4,%5,%6,%7},{%8,%9},{%0,%1,%2,%3};"
        : "+f"(d[0]), "+f"(d[1]), "+f"(d[2]), "+f"(d[3])
        : "r"(a0), "r"(a1), "r"(a2), "r"(a3), "r"(b0), "r"(b1));
}

#define CP_COMMIT() asm volatile("cp.async.commit_group;" ::: "memory")
#define CP_WAIT(N)  asm volatile("cp.async.wait_group %0;" :: "n"(N) : "memory")

// Single extern-shared symbol for the whole TU
extern __shared__ char smem_c[];

// ---------------------------------------------------------------------------
// K0: basis composition -> W^T fp16 [r][o][k]  (+ idx-width detect)
// ---------------------------------------------------------------------------
__global__ void basis_kernel(const float* __restrict__ weight,
                             const float* __restrict__ w_comp,
                             const void* __restrict__ srcv,
                             const void* __restrict__ dstv) {
    if (blockIdx.x == 0 && threadIdx.x == 0) {
        const unsigned* s = (const unsigned*)srcv;
        const unsigned* d = (const unsigned*)dstv;
        int s64 = 1, d64 = 1;
        #pragma unroll
        for (int i = 1; i < 32; i += 2) {
            if (s[i] != 0u) s64 = 0;
            if (d[i] != 0u) d64 = 0;
        }
        g_src64 = s64;
        g_dst64 = d64;
    }
    int gid = blockIdx.x * blockDim.x + threadIdx.x;
    if (gid >= NUM_RELS * OUT_F * (IN_F / 2)) return;
    int r   = gid >> 13;          // / (128*64)
    int rem = gid & 8191;
    int o   = rem >> 6;
    int k   = (rem & 63) * 2;
    float a0 = 0.f, a1 = 0.f;
    #pragma unroll
    for (int b = 0; b < NUM_BASES; b++) {
        float c = __ldg(&w_comp[r * NUM_BASES + b]);
        a0 = fmaf(c, __ldg(&weight[(b << 14) + k * OUT_F + o]), a0);
        a1 = fmaf(c, __ldg(&weight[(b << 14) + (k + 1) * OUT_F + o]), a1);
    }
    size_t idx = (size_t)r * 16384 + o * 128 + k;
    *(__half2*)&g_WH[idx] = __floats2half2_rn(a0, a1);
}

// ---------------------------------------------------------------------------
// K0b: feat -> tf32 copy (selfloop) + fp16 copy (edge)
// ---------------------------------------------------------------------------
__global__ void split_feat_kernel(const float* __restrict__ feat, int n4) {
    int i = blockIdx.x * blockDim.x + threadIdx.x;
    if (i >= n4) return;
    float4 v = ((const float4*)feat)[i];
    float4 t;
    t.x = f2tf(v.x); t.y = f2tf(v.y); t.z = f2tf(v.z); t.w = f2tf(v.w);
    ((float4*)g_featT)[i] = t;
    __half2* hp = (__half2*)g_featH;
    hp[i * 2 + 0] = __floats2half2_rn(v.x, v.y);
    hp[i * 2 + 1] = __floats2half2_rn(v.z, v.w);
}

// ---------------------------------------------------------------------------
// K1: self-loop  out[n] = bias + feat[n] @ loop_weight   (tf32 MMA, 8 warps)
// ---------------------------------------------------------------------------
__global__ void __launch_bounds__(256, 1)
selfloop_mma_kernel(const float* __restrict__ lw,
                    const float* __restrict__ bias,
                    float* __restrict__ out, int n_nodes) {
    float* smem = (float*)smem_c;
    float* Ws = smem;                    // 128 * WSTR
    float* As = smem + 128 * WSTR;       // 128 * ASTR
    int tid = threadIdx.x, warp = tid >> 5, lane = tid & 31;

    const float4* Wg = (const float4*)lw;
    for (int i = tid; i < 4096; i += 256) {
        float4 v = Wg[i];
        v.x = f2tf(v.x); v.y = f2tf(v.y); v.z = f2tf(v.z); v.w = f2tf(v.w);
        int r = i >> 5, c4 = i & 31;
        ((float4*)(Ws + r * WSTR))[c4] = v;
    }

    int nodeBase = blockIdx.x * 128;
    {
        int row = tid >> 1, half = tid & 1;
        int n = nodeBase + row;
        if (n >= n_nodes) n = n_nodes - 1;
        const float4* srow = (const float4*)(g_featT + (long)n * IN_F + half * 64);
        float4* drow = (float4*)(As + row * ASTR + half * 64);
        #pragma unroll
        for (int i = 0; i < 16; i++) drow[i] = srow[i];
    }
    __syncthreads();

    float acc[2][8][4];
    #pragma unroll
    for (int mb = 0; mb < 2; mb++)
        #pragma unroll
        for (int nt = 0; nt < 8; nt++)
            #pragma unroll
            for (int q = 0; q < 4; q++) acc[mb][nt][q] = 0.0f;

    const int gid = lane >> 2, ctg = lane & 3;
    const int wm = warp & 3, wn = warp >> 2;
    const unsigned* Ab = (const unsigned*)As + (wm * 32 + gid) * ASTR + ctg;
    const unsigned* Bb = (const unsigned*)Ws + ctg * WSTR + wn * 64 + gid;
    #pragma unroll
    for (int ks = 0; ks < 16; ks++) {
        unsigned a[2][4], b[8][2];
        #pragma unroll
        for (int mb = 0; mb < 2; mb++) {
            const unsigned* p = Ab + mb * 16 * ASTR + ks * 8;
            a[mb][0] = p[0]; a[mb][1] = p[8 * ASTR];
            a[mb][2] = p[4]; a[mb][3] = p[8 * ASTR + 4];
        }
        #pragma unroll
        for (int nt = 0; nt < 8; nt++) {
            const unsigned* p = Bb + ks * 8 * WSTR + nt * 8;
            b[nt][0] = p[0]; b[nt][1] = p[4 * WSTR];
        }
        #pragma unroll
        for (int mb = 0; mb < 2; mb++)
            #pragma unroll
            for (int nt = 0; nt < 8; nt++)
                mma8(acc[mb][nt], a[mb][0], a[mb][1], a[mb][2], a[mb][3],
                     b[nt][0], b[nt][1]);
    }

    #pragma unroll
    for (int mb = 0; mb < 2; mb++) {
        #pragma unroll
        for (int nt = 0; nt < 8; nt++) {
            int r = wm * 32 + mb * 16 + gid;
            int c = wn * 64 + nt * 8 + 2 * ctg;
            float2 b2 = *(const float2*)(bias + c);
            int n0 = nodeBase + r;
            if (n0 < n_nodes)
                *(float2*)(out + (long)n0 * OUT_F + c) =
                    make_float2(acc[mb][nt][0] + b2.x, acc[mb][nt][1] + b2.y);
            int n1 = nodeBase + r + 8;
            if (n1 < n_nodes)
                *(float2*)(out + (long)n1 * OUT_F + c) =
                    make_float2(acc[mb][nt][2] + b2.x, acc[mb][nt][3] + b2.y);
        }
    }
}

// ---------------------------------------------------------------------------
// K2: edge grouped GEMM (fp16 m16n8k16) + atomic scatter, 2 CTAs/SM.
// Block = 1024 edges (one relation), 8 tiles of 128, double-buffered cp.async.
// SMEM (bytes): Ws 0..34815 | A0 34816.. | A1 69632.. | dst 104448 | nrm 105472
// total 106496 B/CTA -> 2 CTAs/SM.
// ---------------------------------------------------------------------------
#define EDGE_SMEM_BYTES 106496

__device__ __forceinline__ void gather_tile_h(char* Abuf, int* dsts, float* nrms,
                                              const void* srcv, const void* dstv,
                                              const float* norm, long e0,
                                              int s64, int d64, int tid) {
    int row = tid >> 1, half = tid & 1;
    long e = e0 + row;
    long sidx = s64 ? (long)((const long long*)srcv)[e]
                    : (long)((const int*)srcv)[e];
    const char* srow = (const char*)g_featH + sidx * 256 + half * 128;
    unsigned daddr =
        (unsigned)__cvta_generic_to_shared(Abuf + row * 272 + half * 128);
    #pragma unroll
    for (int i = 0; i < 8; i++)
        asm volatile("cp.async.cg.shared.global [%0], [%1], 16;" ::
                     "r"(daddr + i * 16), "l"(srow + i * 16));
    if (tid < 128) {
        long ee = e0 + tid;
        dsts[tid] = d64 ? (int)((const long long*)dstv)[ee]
                        : ((const int*)dstv)[ee];
        nrms[tid] = norm[ee];
    }
}

__global__ void __launch_bounds__(256, 2)
edge_mma_kernel(const void* __restrict__ srcv,
                const void* __restrict__ dstv,
                const float* __restrict__ norm,
                float* __restrict__ out, int section) {
    char* smem = smem_c;
    char* Ws = smem;                         // 128 rows x 272 B
    char* A0 = smem + 34816;
    char* A1 = smem + 69632;
    int*   dst_s = (int*)(smem + 104448);    // [2][128]
    float* nrm_s = (float*)(smem + 105472);  // [2][128]

    int tid = threadIdx.x, warp = tid >> 5, lane = tid & 31;
    long eBase = (long)blockIdx.x * 1024;
    int rel = (int)(eBase / section);

    // Prologue: W^T fp16 (cp.async) + gather tile0 -> buf0, one commit group.
    {
        const char* Wg = (const char*)(g_WH + (size_t)rel * 16384);
        int row = tid >> 1, half = tid & 1;
        unsigned daddr =
            (unsigned)__cvta_generic_to_shared(Ws + row * 272 + half * 128);
        const char* srow = Wg + row * 256 + half * 128;
        #pragma unroll
        for (int i = 0; i < 8; i++)
            asm volatile("cp.async.cg.shared.global [%0], [%1], 16;" ::
                         "r"(daddr + i * 16), "l"(srow + i * 16));
    }
    const int s64 = g_src64, d64 = g_dst64;
    gather_tile_h(A0, dst_s, nrm_s, srcv, dstv, norm, eBase, s64, d64, tid);
    CP_COMMIT();

    const int gid = lane >> 2, ctg = lane & 3;
    const int wm = warp & 3, wn = warp >> 2;
    char* Ab[2] = {A0, A1};

    #pragma unroll 1
    for (int t = 0; t < 8; t++) {
        int b = t & 1;
        __syncthreads();   // protect buf b^1 (readers from iter t-1 done)
        if (t < 7) {
            gather_tile_h(Ab[b ^ 1], dst_s + (b ^ 1) * 128,
                          nrm_s + (b ^ 1) * 128, srcv, dstv, norm,
                          eBase + (long)(t + 1) * 128, s64, d64, tid);
            CP_COMMIT();
            CP_WAIT(1);    // buf b's group complete
        } else {
            CP_WAIT(0);
        }
        __syncthreads();   // all threads' gathers for buf b visible

        float acc[2][8][4];
        #pragma unroll
        for (int mb = 0; mb < 2; mb++)
            #pragma unroll
            for (int nt = 0; nt < 8; nt++)
                #pragma unroll
                for (int q = 0; q < 4; q++) acc[mb][nt][q] = 0.0f;

        // fp16 mainloop: K=128 in 8 k16 slices.
        {
            const unsigned* Aw =
                (const unsigned*)(Ab[b]) + (wm * 32 + gid) * RSTRW + ctg;
            const unsigned* Bw =
                (const unsigned*)Ws + (wn * 64 + gid) * RSTRW + ctg;
            #pragma unroll
            for (int ks = 0; ks < 8; ks++) {
                unsigned a[2][4], bb[8][2];
                #pragma unroll
                for (int mb = 0; mb < 2; mb++) {
                    const unsigned* p = Aw + mb * 16 * RSTRW + ks * 8;
                    a[mb][0] = p[0];
                    a[mb][1] = p[8 * RSTRW];
                    a[mb][2] = p[4];
                    a[mb][3] = p[8 * RSTRW + 4];
                }
                #pragma unroll
                for (int nt = 0; nt < 8; nt++) {
                    const unsigned* q = Bw + nt * 8 * RSTRW + ks * 8;
                    bb[nt][0] = q[0];
                    bb[nt][1] = q[4];
                }
                #pragma unroll
                for (int mb = 0; mb < 2; mb++)
                    #pragma unroll
                    for (int nt = 0; nt < 8; nt++)
                        mma16(acc[mb][nt], a[mb][0], a[mb][1], a[mb][2],
                              a[mb][3], bb[nt][0], bb[nt][1]);
            }
        }

        // Fragment-direct epilogue: scale by norm, shfl-merge lane pairs,
        // half-warp float4 atomics.
        const int* mydst = dst_s + b * 128;
        const float* mynrm = nrm_s + b * 128;
        #pragma unroll
        for (int mb = 0; mb < 2; mb++) {
            int r0 = wm * 32 + mb * 16 + gid;
            int r1 = r0 + 8;
            float nv0 = mynrm[r0], nv1 = mynrm[r1];
            long d0 = mydst[r0], d1 = mydst[r1];
            #pragma unroll
            for (int nt = 0; nt < 8; nt++) {
                float x0 = acc[mb][nt][0] * nv0, x1 = acc[mb][nt][1] * nv0;
                float x2 = acc[mb][nt][2] * nv1, x3 = acc[mb][nt][3] * nv1;
                float y0 = __shfl_xor_sync(0xFFFFFFFFu, x0, 1);
                float y1 = __shfl_xor_sync(0xFFFFFFFFu, x1, 1);
                float y2 = __shfl_xor_sync(0xFFFFFFFFu, x2, 1);
                float y3 = __shfl_xor_sync(0xFFFFFFFFu, x3, 1);
                if (!(lane & 1)) {   // ctg even: owns cols 2ctg..2ctg+3
                    int c = wn * 64 + nt * 8 + 2 * ctg;
                    atomicAdd((float4*)(out + d0 * OUT_F + c),
                              make_float4(x0, x1, y0, y1));
                    atomicAdd((float4*)(out + d1 * OUT_F + c),
                              make_float4(x2, x3, y2, y3));
                }
            }
        }
    }
}

// ---------------------------------------------------------------------------
// K3: relu in place
// ---------------------------------------------------------------------------
__global__ void relu_kernel(float* __restrict__ out, int n4) {
    int i = blockIdx.x * blockDim.x + threadIdx.x;
    if (i < n4) {
        float4 v = ((float4*)out)[i];
        v.x = fmaxf(v.x, 0.f);
        v.y = fmaxf(v.y, 0.f);
        v.z = fmaxf(v.z, 0.f);
        v.w = fmaxf(v.w, 0.f);
        ((float4*)out)[i] = v;
    }
}

// ---------------------------------------------------------------------------
extern "C" void kernel_launch(void* const* d_in, const int* in_sizes, int n_in,
                              void* d_out, int out_size) {
    const float* feat        = (const float*)d_in[0];
    const float* weight      = (const float*)d_in[1];
    const float* w_comp      = (const float*)d_in[2];
    const float* h_bias      = (const float*)d_in[3];
    const float* loop_weight = (const float*)d_in[4];
    const float* norm        = (const float*)d_in[5];
    const void*  src         = d_in[6];
    const void*  dst         = d_in[7];

    const int E       = in_sizes[5];
    const int n_nodes = in_sizes[0] / IN_F;
    const int section = E / NUM_RELS;

    float* out = (float*)d_out;

    const int SMEM_SELF = (128 * WSTR + 128 * ASTR) * 4;   // ~134 KB
    cudaFuncSetAttribute(selfloop_mma_kernel,
                         cudaFuncAttributeMaxDynamicSharedMemorySize, SMEM_SELF);
    cudaFuncSetAttribute(edge_mma_kernel,
                         cudaFuncAttributeMaxDynamicSharedMemorySize, EDGE_SMEM_BYTES);

    // K0: basis composition (W^T fp16) + index detect
    basis_kernel<<<(NUM_RELS * OUT_F * (IN_F / 2) + 255) / 256, 256>>>(weight, w_comp, src, dst);

    // K0b: feat -> tf32 + fp16
    int n4 = n_nodes * (IN_F / 4);
    split_feat_kernel<<<(n4 + 255) / 256, 256>>>(feat, n4);

    // K1: self-loop (initializes out)
    selfloop_mma_kernel<<<(n_nodes + 127) / 128, 256, SMEM_SELF>>>(loop_weight, h_bias, out, n_nodes);

    // K2: edge grouped GEMM (fp16) + atomic scatter
    edge_mma_kernel<<<E / 1024, 256, EDGE_SMEM_BYTES>>>(src, dst, norm, out, section);

    // K3: relu
    relu_kernel<<<(n_nodes * (OUT_F / 4) + 255) / 256, 256>>>(out, n_nodes * (OUT_F / 4));
}

// round 15
// speedup vs baseline: 1.7895x; 1.1396x over previous
#include <cuda_runtime.h>
#include <cuda_fp16.h>
#include <stdint.h>

// Problem constants (fixed by the dataset)
#define NUM_RELS   64
#define NUM_BASES  16
#define IN_F       128
#define OUT_F      128
#define N_CAP      100352          // >= n_nodes (100000)

#define RSTRB 272                  // fp16 tile row stride in bytes (256 data + 16 pad)
#define RSTRH 136                  // ... in halfs

// Scratch (static device globals; no allocations)
__device__ __half g_featH[(size_t)N_CAP * IN_F];  // fp16 feat
__device__ __half g_WH[NUM_RELS * OUT_F * IN_F];  // W^T fp16, [r][o][k]
__device__ int g_src64;
__device__ int g_dst64;

// ---------------------------------------------------------------------------
// helpers
// ---------------------------------------------------------------------------
// fp16 m16n8k16
__device__ __forceinline__ void mma16(float d[4], unsigned a0, unsigned a1,
                                      unsigned a2, unsigned a3,
                                      unsigned b0, unsigned b1) {
    asm("mma.sync.aligned.m16n8k16.row.col.f32.f16.f16.f32 "
        "{%0,%1,%2,%3},{%4,%5,%6,%7},{%8,%9},{%0,%1,%2,%3};"
        : "+f"(d[0]), "+f"(d[1]), "+f"(d[2]), "+f"(d[3])
        : "r"(a0), "r"(a1), "r"(a2), "r"(a3), "r"(b0), "r"(b1));
}

#define LDSM_X4(r0, r1, r2, r3, addr) \
    asm volatile("ldmatrix.sync.aligned.m8n8.x4.shared.b16 {%0,%1,%2,%3}, [%4];" \
        : "=r"(r0), "=r"(r1), "=r"(r2), "=r"(r3) : "r"(addr))

#define CP_COMMIT() asm volatile("cp.async.commit_group;" ::: "memory")
#define CP_WAIT(N)  asm volatile("cp.async.wait_group %0;" :: "n"(N) : "memory")

// Single extern-shared symbol for the whole TU
extern __shared__ char smem_c[];

__device__ __forceinline__ unsigned smem_u32(const void* p) {
    return (unsigned)__cvta_generic_to_shared(p);
}

// fp16 warp-tile mainloop via ldmatrix: 32x64 per warp, K=128 in 8 k16 slices.
// Atile/Wtile: 128 rows x RSTRB bytes (A rows = edges/nodes, W rows = out cols).
__device__ __forceinline__ void mma_tile_h(unsigned aBase, unsigned bBase,
                                           int warp, int lane, float acc[2][8][4]) {
    const int wm = warp & 3, wn = warp >> 2;
    // A x4: lanes 0-15 -> rows (lane&15) at k-byte 0; lanes 16-31 -> same rows, k-byte 16
    unsigned aAddr = aBase + (unsigned)((wm * 32 + (lane & 15)) * RSTRB + (lane >> 4) * 16);
    // B x4: group g = lane>>3: row = (g>>1)*8 + (lane&7), byte = (g&1)*16
    unsigned bAddr = bBase + (unsigned)((wn * 64 + ((lane >> 4) << 3) + (lane & 7)) * RSTRB
                                        + (((lane >> 3) & 1) << 4));
    #pragma unroll
    for (int ks = 0; ks < 8; ks++) {
        unsigned a[2][4], b[4][4];
        #pragma unroll
        for (int mb = 0; mb < 2; mb++)
            LDSM_X4(a[mb][0], a[mb][1], a[mb][2], a[mb][3],
                    aAddr + mb * 16 * RSTRB + ks * 32);
        #pragma unroll
        for (int np = 0; np < 4; np++)
            LDSM_X4(b[np][0], b[np][1], b[np][2], b[np][3],
                    bAddr + np * 16 * RSTRB + ks * 32);
        #pragma unroll
        for (int mb = 0; mb < 2; mb++) {
            #pragma unroll
            for (int np = 0; np < 4; np++) {
                mma16(acc[mb][2 * np + 0], a[mb][0], a[mb][1], a[mb][2], a[mb][3],
                      b[np][0], b[np][1]);
                mma16(acc[mb][2 * np + 1], a[mb][0], a[mb][1], a[mb][2], a[mb][3],
                      b[np][2], b[np][3]);
            }
        }
    }
}

// ---------------------------------------------------------------------------
// K0: basis composition -> W^T fp16 [r][o][k]  (+ idx-width detect)
// ---------------------------------------------------------------------------
__global__ void basis_kernel(const float* __restrict__ weight,
                             const float* __restrict__ w_comp,
                             const void* __restrict__ srcv,
                             const void* __restrict__ dstv) {
    if (blockIdx.x == 0 && threadIdx.x == 0) {
        const unsigned* s = (const unsigned*)srcv;
        const unsigned* d = (const unsigned*)dstv;
        int s64 = 1, d64 = 1;
        #pragma unroll
        for (int i = 1; i < 32; i += 2) {
            if (s[i] != 0u) s64 = 0;
            if (d[i] != 0u) d64 = 0;
        }
        g_src64 = s64;
        g_dst64 = d64;
    }
    int gid = blockIdx.x * blockDim.x + threadIdx.x;
    if (gid >= NUM_RELS * OUT_F * (IN_F / 2)) return;
    int r   = gid >> 13;          // / (128*64)
    int rem = gid & 8191;
    int o   = rem >> 6;
    int k   = (rem & 63) * 2;
    float a0 = 0.f, a1 = 0.f;
    #pragma unroll
    for (int b = 0; b < NUM_BASES; b++) {
        float c = __ldg(&w_comp[r * NUM_BASES + b]);
        a0 = fmaf(c, __ldg(&weight[(b << 14) + k * OUT_F + o]), a0);
        a1 = fmaf(c, __ldg(&weight[(b << 14) + (k + 1) * OUT_F + o]), a1);
    }
    size_t idx = (size_t)r * 16384 + o * 128 + k;
    *(__half2*)&g_WH[idx] = __floats2half2_rn(a0, a1);
}

// ---------------------------------------------------------------------------
// K0b: feat -> fp16
// ---------------------------------------------------------------------------
__global__ void half_feat_kernel(const float* __restrict__ feat, int n4) {
    int i = blockIdx.x * blockDim.x + threadIdx.x;
    if (i >= n4) return;
    float4 v = ((const float4*)feat)[i];
    __half2* hp = (__half2*)g_featH;
    hp[i * 2 + 0] = __floats2half2_rn(v.x, v.y);
    hp[i * 2 + 1] = __floats2half2_rn(v.z, v.w);
}

// ---------------------------------------------------------------------------
// K1: self-loop  out[n] = bias + feat[n] @ loop_weight  (fp16 MMA, 2 CTAs/SM)
// smem: Ws [128 x RSTRB] 34816 B | As [128 x RSTRB] 34816 B  = 69632 B
// ---------------------------------------------------------------------------
#define SELF_SMEM_BYTES 69632

__global__ void __launch_bounds__(256, 2)
selfloop_mma_kernel(const float* __restrict__ lw,
                    const float* __restrict__ bias,
                    float* __restrict__ out, int n_nodes) {
    char* smem = smem_c;
    __half* Wsh = (__half*)smem;             // rows = out col c, cols = k
    char*   As  = smem + 34816;
    int tid = threadIdx.x, warp = tid >> 5, lane = tid & 31;

    // lw [k][c] f32 -> Wsh[c][k] fp16 (transposed)
    for (int i = tid; i < 16384; i += 256) {
        int k = i >> 7, c = i & 127;
        Wsh[c * RSTRH + k] = __float2half_rn(__ldg(&lw[i]));
    }

    // Gather 128 node rows (fp16, 256 B each) via cp.async
    int nodeBase = blockIdx.x * 128;
    {
        int row = tid >> 1, half = tid & 1;
        int n = nodeBase + row;
        if (n >= n_nodes) n = n_nodes - 1;
        const char* srow = (const char*)g_featH + (long)n * 256 + half * 128;
        unsigned daddr = smem_u32(As + row * RSTRB + half * 128);
        #pragma unroll
        for (int i = 0; i < 8; i++)
            asm volatile("cp.async.cg.shared.global [%0], [%1], 16;" ::
                         "r"(daddr + i * 16), "l"(srow + i * 16));
    }
    CP_COMMIT(); CP_WAIT(0);
    __syncthreads();

    float acc[2][8][4];
    #pragma unroll
    for (int mb = 0; mb < 2; mb++)
        #pragma unroll
        for (int nt = 0; nt < 8; nt++)
            #pragma unroll
            for (int q = 0; q < 4; q++) acc[mb][nt][q] = 0.0f;

    mma_tile_h(smem_u32(As), smem_u32(smem), warp, lane, acc);

    const int gid = lane >> 2, ctg = lane & 3;
    const int wm = warp & 3, wn = warp >> 2;
    #pragma unroll
    for (int mb = 0; mb < 2; mb++) {
        #pragma unroll
        for (int nt = 0; nt < 8; nt++) {
            int r = wm * 32 + mb * 16 + gid;
            int c = wn * 64 + nt * 8 + 2 * ctg;
            float2 b2 = *(const float2*)(bias + c);
            int n0 = nodeBase + r;
            if (n0 < n_nodes)
                *(float2*)(out + (long)n0 * OUT_F + c) =
                    make_float2(acc[mb][nt][0] + b2.x, acc[mb][nt][1] + b2.y);
            int n1 = nodeBase + r + 8;
            if (n1 < n_nodes)
                *(float2*)(out + (long)n1 * OUT_F + c) =
                    make_float2(acc[mb][nt][2] + b2.x, acc[mb][nt][3] + b2.y);
        }
    }
}

// ---------------------------------------------------------------------------
// K2: edge grouped GEMM (fp16 + ldmatrix) + atomic scatter, 2 CTAs/SM.
// Block = 1024 edges (one relation), 8 tiles of 128, double-buffered cp.async.
// SMEM: Ws 0..34815 | A0 34816.. | A1 69632.. | dst 104448 | nrm 105472
// ---------------------------------------------------------------------------
#define EDGE_SMEM_BYTES 106496

__device__ __forceinline__ void gather_tile_h(char* Abuf, int* dsts, float* nrms,
                                              const void* srcv, const void* dstv,
                                              const float* norm, long e0,
                                              int s64, int d64, int tid) {
    int row = tid >> 1, half = tid & 1;
    long e = e0 + row;
    long sidx = s64 ? (long)((const long long*)srcv)[e]
                    : (long)((const int*)srcv)[e];
    const char* srow = (const char*)g_featH + sidx * 256 + half * 128;
    unsigned daddr = smem_u32(Abuf + row * RSTRB + half * 128);
    #pragma unroll
    for (int i = 0; i < 8; i++)
        asm volatile("cp.async.cg.shared.global [%0], [%1], 16;" ::
                     "r"(daddr + i * 16), "l"(srow + i * 16));
    if (tid < 128) {
        long ee = e0 + tid;
        dsts[tid] = d64 ? (int)((const long long*)dstv)[ee]
                        : ((const int*)dstv)[ee];
        nrms[tid] = norm[ee];
    }
}

__global__ void __launch_bounds__(256, 2)
edge_mma_kernel(const void* __restrict__ srcv,
                const void* __restrict__ dstv,
                const float* __restrict__ norm,
                float* __restrict__ out, int section) {
    char* smem = smem_c;
    char* Ws = smem;                         // 128 rows x 272 B
    char* A0 = smem + 34816;
    char* A1 = smem + 69632;
    int*   dst_s = (int*)(smem + 104448);    // [2][128]
    float* nrm_s = (float*)(smem + 105472);  // [2][128]

    int tid = threadIdx.x, warp = tid >> 5, lane = tid & 31;
    long eBase = (long)blockIdx.x * 1024;
    int rel = (int)(eBase / section);

    // Prologue: W^T fp16 (cp.async) + gather tile0 -> buf0, one commit group.
    {
        const char* Wg = (const char*)(g_WH + (size_t)rel * 16384);
        int row = tid >> 1, half = tid & 1;
        unsigned daddr = smem_u32(Ws + row * RSTRB + half * 128);
        const char* srow = Wg + row * 256 + half * 128;
        #pragma unroll
        for (int i = 0; i < 8; i++)
            asm volatile("cp.async.cg.shared.global [%0], [%1], 16;" ::
                         "r"(daddr + i * 16), "l"(srow + i * 16));
    }
    const int s64 = g_src64, d64 = g_dst64;
    gather_tile_h(A0, dst_s, nrm_s, srcv, dstv, norm, eBase, s64, d64, tid);
    CP_COMMIT();

    const int gid = lane >> 2, ctg = lane & 3;
    const int wm = warp & 3, wn = warp >> 2;
    char* Ab[2] = {A0, A1};
    unsigned wsAddr = smem_u32(Ws);

    #pragma unroll 1
    for (int t = 0; t < 8; t++) {
        int b = t & 1;
        __syncthreads();   // protect buf b^1 (readers from iter t-1 done)
        if (t < 7) {
            gather_tile_h(Ab[b ^ 1], dst_s + (b ^ 1) * 128,
                          nrm_s + (b ^ 1) * 128, srcv, dstv, norm,
                          eBase + (long)(t + 1) * 128, s64, d64, tid);
            CP_COMMIT();
            CP_WAIT(1);    // buf b's group complete
        } else {
            CP_WAIT(0);
        }
        __syncthreads();   // all threads' gathers for buf b visible

        float acc[2][8][4];
        #pragma unroll
        for (int mb = 0; mb < 2; mb++)
            #pragma unroll
            for (int nt = 0; nt < 8; nt++)
                #pragma unroll
                for (int q = 0; q < 4; q++) acc[mb][nt][q] = 0.0f;

        mma_tile_h(smem_u32(Ab[b]), wsAddr, warp, lane, acc);

        // Fragment-direct epilogue: scale by norm, shfl-merge lane pairs,
        // half-warp float4 atomics.
        const int* mydst = dst_s + b * 128;
        const float* mynrm = nrm_s + b * 128;
        #pragma unroll
        for (int mb = 0; mb < 2; mb++) {
            int r0 = wm * 32 + mb * 16 + gid;
            int r1 = r0 + 8;
            float nv0 = mynrm[r0], nv1 = mynrm[r1];
            long d0 = mydst[r0], d1 = mydst[r1];
            #pragma unroll
            for (int nt = 0; nt < 8; nt++) {
                float x0 = acc[mb][nt][0] * nv0, x1 = acc[mb][nt][1] * nv0;
                float x2 = acc[mb][nt][2] * nv1, x3 = acc[mb][nt][3] * nv1;
                float y0 = __shfl_xor_sync(0xFFFFFFFFu, x0, 1);
                float y1 = __shfl_xor_sync(0xFFFFFFFFu, x1, 1);
                float y2 = __shfl_xor_sync(0xFFFFFFFFu, x2, 1);
                float y3 = __shfl_xor_sync(0xFFFFFFFFu, x3, 1);
                if (!(lane & 1)) {   // ctg even: owns cols 2ctg..2ctg+3
                    int c = wn * 64 + nt * 8 + 2 * ctg;
                    atomicAdd((float4*)(out + d0 * OUT_F + c),
                              make_float4(x0, x1, y0, y1));
                    atomicAdd((float4*)(out + d1 * OUT_F + c),
                              make_float4(x2, x3, y2, y3));
                }
            }
        }
    }
}

// ---------------------------------------------------------------------------
// K3: relu in place
// ---------------------------------------------------------------------------
__global__ void relu_kernel(float* __restrict__ out, int n4) {
    int i = blockIdx.x * blockDim.x + threadIdx.x;
    if (i < n4) {
        float4 v = ((float4*)out)[i];
        v.x = fmaxf(v.x, 0.f);
        v.y = fmaxf(v.y, 0.f);
        v.z = fmaxf(v.z, 0.f);
        v.w = fmaxf(v.w, 0.f);
        ((float4*)out)[i] = v;
    }
}

// ---------------------------------------------------------------------------
extern "C" void kernel_launch(void* const* d_in, const int* in_sizes, int n_in,
                              void* d_out, int out_size) {
    const float* feat        = (const float*)d_in[0];
    const float* weight      = (const float*)d_in[1];
    const float* w_comp      = (const float*)d_in[2];
    const float* h_bias      = (const float*)d_in[3];
    const float* loop_weight = (const float*)d_in[4];
    const float* norm        = (const float*)d_in[5];
    const void*  src         = d_in[6];
    const void*  dst         = d_in[7];

    const int E       = in_sizes[5];
    const int n_nodes = in_sizes[0] / IN_F;
    const int section = E / NUM_RELS;

    float* out = (float*)d_out;

    cudaFuncSetAttribute(selfloop_mma_kernel,
                         cudaFuncAttributeMaxDynamicSharedMemorySize, SELF_SMEM_BYTES);
    cudaFuncSetAttribute(edge_mma_kernel,
                         cudaFuncAttributeMaxDynamicSharedMemorySize, EDGE_SMEM_BYTES);

    // K0: basis composition (W^T fp16) + index detect
    basis_kernel<<<(NUM_RELS * OUT_F * (IN_F / 2) + 255) / 256, 256>>>(weight, w_comp, src, dst);

    // K0b: feat -> fp16
    int n4 = n_nodes * (IN_F / 4);
    half_feat_kernel<<<(n4 + 255) / 256, 256>>>(feat, n4);

    // K1: self-loop (initializes out)
    selfloop_mma_kernel<<<(n_nodes + 127) / 128, 256, SELF_SMEM_BYTES>>>(loop_weight, h_bias, out, n_nodes);

    // K2: edge grouped GEMM (fp16 + ldmatrix) + atomic scatter
    edge_mma_kernel<<<E / 1024, 256, EDGE_SMEM_BYTES>>>(src, dst, norm, out, section);

    // K3: relu
    relu_kernel<<<(n_nodes * (OUT_F / 4) + 255) / 256, 256>>>(out, n_nodes * (OUT_F / 4));
}

// round 16
// speedup vs baseline: 1.8945x; 1.0587x over previous
#include <cuda_runtime.h>
#include <cuda_fp16.h>
#include <stdint.h>

// Problem constants (fixed by the dataset)
#define NUM_RELS   64
#define NUM_BASES  16
#define IN_F       128
#define OUT_F      128
#define N_CAP      100352          // >= n_nodes (100000)

#define RSTRB 272                  // fp16 tile row stride in bytes (256 data + 16 pad)
#define RSTRH 136                  // ... in halfs

// Scratch (static device globals; no allocations)
__device__ __half g_featH[(size_t)N_CAP * IN_F];  // fp16 feat
__device__ __half g_WH[NUM_RELS * OUT_F * IN_F];  // W^T fp16, [r][o][k]
__device__ int g_src64;
__device__ int g_dst64;

// ---------------------------------------------------------------------------
// helpers
// ---------------------------------------------------------------------------
// fp16 m16n8k16
__device__ __forceinline__ void mma16(float d[4], unsigned a0, unsigned a1,
                                      unsigned a2, unsigned a3,
                                      unsigned b0, unsigned b1) {
    asm("mma.sync.aligned.m16n8k16.row.col.f32.f16.f16.f32 "
        "{%0,%1,%2,%3},{%4,%5,%6,%7},{%8,%9},{%0,%1,%2,%3};"
        : "+f"(d[0]), "+f"(d[1]), "+f"(d[2]), "+f"(d[3])
        : "r"(a0), "r"(a1), "r"(a2), "r"(a3), "r"(b0), "r"(b1));
}

#define LDSM_X4(r0, r1, r2, r3, addr) \
    asm volatile("ldmatrix.sync.aligned.m8n8.x4.shared.b16 {%0,%1,%2,%3}, [%4];" \
        : "=r"(r0), "=r"(r1), "=r"(r2), "=r"(r3) : "r"(addr))

#define CP_COMMIT() asm volatile("cp.async.commit_group;" ::: "memory")
#define CP_WAIT(N)  asm volatile("cp.async.wait_group %0;" :: "n"(N) : "memory")

// Single extern-shared symbol for the whole TU
extern __shared__ char smem_c[];

__device__ __forceinline__ unsigned smem_u32(const void* p) {
    return (unsigned)__cvta_generic_to_shared(p);
}

// fp16 warp-tile mainloop via ldmatrix: 32x64 per warp, K=128 in 8 k16 slices.
// Atile/Wtile: 128 rows x RSTRB bytes (A rows = edges/nodes, W rows = out cols).
__device__ __forceinline__ void mma_tile_h(unsigned aBase, unsigned bBase,
                                           int warp, int lane, float acc[2][8][4]) {
    const int wm = warp & 3, wn = warp >> 2;
    // A x4: lanes 0-15 -> rows (lane&15) at k-byte 0; lanes 16-31 -> same rows, k-byte 16
    unsigned aAddr = aBase + (unsigned)((wm * 32 + (lane & 15)) * RSTRB + (lane >> 4) * 16);
    // B x4: group g = lane>>3: row = (g>>1)*8 + (lane&7), byte = (g&1)*16
    unsigned bAddr = bBase + (unsigned)((wn * 64 + ((lane >> 4) << 3) + (lane & 7)) * RSTRB
                                        + (((lane >> 3) & 1) << 4));
    #pragma unroll
    for (int ks = 0; ks < 8; ks++) {
        unsigned a[2][4], b[4][4];
        #pragma unroll
        for (int mb = 0; mb < 2; mb++)
            LDSM_X4(a[mb][0], a[mb][1], a[mb][2], a[mb][3],
                    aAddr + mb * 16 * RSTRB + ks * 32);
        #pragma unroll
        for (int np = 0; np < 4; np++)
            LDSM_X4(b[np][0], b[np][1], b[np][2], b[np][3],
                    bAddr + np * 16 * RSTRB + ks * 32);
        #pragma unroll
        for (int mb = 0; mb < 2; mb++) {
            #pragma unroll
            for (int np = 0; np < 4; np++) {
                mma16(acc[mb][2 * np + 0], a[mb][0], a[mb][1], a[mb][2], a[mb][3],
                      b[np][0], b[np][1]);
                mma16(acc[mb][2 * np + 1], a[mb][0], a[mb][1], a[mb][2], a[mb][3],
                      b[np][2], b[np][3]);
            }
        }
    }
}

// ---------------------------------------------------------------------------
// K0: basis composition -> W^T fp16 [r][o][k]  (+ idx-width detect)
// ---------------------------------------------------------------------------
__global__ void basis_kernel(const float* __restrict__ weight,
                             const float* __restrict__ w_comp,
                             const void* __restrict__ srcv,
                             const void* __restrict__ dstv) {
    if (blockIdx.x == 0 && threadIdx.x == 0) {
        const unsigned* s = (const unsigned*)srcv;
        const unsigned* d = (const unsigned*)dstv;
        int s64 = 1, d64 = 1;
        #pragma unroll
        for (int i = 1; i < 32; i += 2) {
            if (s[i] != 0u) s64 = 0;
            if (d[i] != 0u) d64 = 0;
        }
        g_src64 = s64;
        g_dst64 = d64;
    }
    int gid = blockIdx.x * blockDim.x + threadIdx.x;
    if (gid >= NUM_RELS * OUT_F * (IN_F / 2)) return;
    int r   = gid >> 13;          // / (128*64)
    int rem = gid & 8191;
    int o   = rem >> 6;
    int k   = (rem & 63) * 2;
    float a0 = 0.f, a1 = 0.f;
    #pragma unroll
    for (int b = 0; b < NUM_BASES; b++) {
        float c = __ldg(&w_comp[r * NUM_BASES + b]);
        a0 = fmaf(c, __ldg(&weight[(b << 14) + k * OUT_F + o]), a0);
        a1 = fmaf(c, __ldg(&weight[(b << 14) + (k + 1) * OUT_F + o]), a1);
    }
    size_t idx = (size_t)r * 16384 + o * 128 + k;
    *(__half2*)&g_WH[idx] = __floats2half2_rn(a0, a1);
}

// ---------------------------------------------------------------------------
// K0b: feat -> fp16
// ---------------------------------------------------------------------------
__global__ void half_feat_kernel(const float* __restrict__ feat, int n4) {
    int i = blockIdx.x * blockDim.x + threadIdx.x;
    if (i >= n4) return;
    float4 v = ((const float4*)feat)[i];
    __half2* hp = (__half2*)g_featH;
    hp[i * 2 + 0] = __floats2half2_rn(v.x, v.y);
    hp[i * 2 + 1] = __floats2half2_rn(v.z, v.w);
}

// ---------------------------------------------------------------------------
// K1: self-loop  out[n] = bias + feat[n] @ loop_weight  (fp16 MMA, 2 CTAs/SM)
// smem: Ws [128 x RSTRB] 34816 B | As [128 x RSTRB] 34816 B  = 69632 B
// ---------------------------------------------------------------------------
#define SELF_SMEM_BYTES 69632

__global__ void __launch_bounds__(256, 2)
selfloop_mma_kernel(const float* __restrict__ lw,
                    const float* __restrict__ bias,
                    float* __restrict__ out, int n_nodes) {
    char* smem = smem_c;
    __half* Wsh = (__half*)smem;             // rows = out col c, cols = k
    char*   As  = smem + 34816;
    int tid = threadIdx.x, warp = tid >> 5, lane = tid & 31;

    // lw [k][c] f32 -> Wsh[c][k] fp16 (transposed)
    for (int i = tid; i < 16384; i += 256) {
        int k = i >> 7, c = i & 127;
        Wsh[c * RSTRH + k] = __float2half_rn(__ldg(&lw[i]));
    }

    // Gather 128 node rows (fp16, 256 B each) via cp.async
    int nodeBase = blockIdx.x * 128;
    {
        int row = tid >> 1, half = tid & 1;
        int n = nodeBase + row;
        if (n >= n_nodes) n = n_nodes - 1;
        const char* srow = (const char*)g_featH + (long)n * 256 + half * 128;
        unsigned daddr = smem_u32(As + row * RSTRB + half * 128);
        #pragma unroll
        for (int i = 0; i < 8; i++)
            asm volatile("cp.async.cg.shared.global [%0], [%1], 16;" ::
                         "r"(daddr + i * 16), "l"(srow + i * 16));
    }
    CP_COMMIT(); CP_WAIT(0);
    __syncthreads();

    float acc[2][8][4];
    #pragma unroll
    for (int mb = 0; mb < 2; mb++)
        #pragma unroll
        for (int nt = 0; nt < 8; nt++)
            #pragma unroll
            for (int q = 0; q < 4; q++) acc[mb][nt][q] = 0.0f;

    mma_tile_h(smem_u32(As), smem_u32(smem), warp, lane, acc);

    const int gid = lane >> 2, ctg = lane & 3;
    const int wm = warp & 3, wn = warp >> 2;
    #pragma unroll
    for (int mb = 0; mb < 2; mb++) {
        #pragma unroll
        for (int nt = 0; nt < 8; nt++) {
            int r = wm * 32 + mb * 16 + gid;
            int c = wn * 64 + nt * 8 + 2 * ctg;
            float2 b2 = *(const float2*)(bias + c);
            int n0 = nodeBase + r;
            if (n0 < n_nodes)
                *(float2*)(out + (long)n0 * OUT_F + c) =
                    make_float2(acc[mb][nt][0] + b2.x, acc[mb][nt][1] + b2.y);
            int n1 = nodeBase + r + 8;
            if (n1 < n_nodes)
                *(float2*)(out + (long)n1 * OUT_F + c) =
                    make_float2(acc[mb][nt][2] + b2.x, acc[mb][nt][3] + b2.y);
        }
    }
}

// ---------------------------------------------------------------------------
// K2: edge grouped GEMM (fp16 + ldmatrix) + warp-coherent row atomics, 2 CTAs/SM.
// Block = 1024 edges (one relation), 8 tiles of 128, double-buffered cp.async.
// SMEM: Ws 0..34815 | A0 34816.. | A1 69632.. | dst 104448 | nrm 105472
// Epilogue: acc -> smem (reuse consumed A buffer, 64 rows/pass) -> each warp
// issues whole-row 512B atomicAdd float4 (32 lanes contiguous = 4 wavefronts).
// ---------------------------------------------------------------------------
#define EDGE_SMEM_BYTES 106496
#define WBSTR 132                  // writeback stride in floats

__device__ __forceinline__ void gather_tile_h(char* Abuf, int* dsts, float* nrms,
                                              const void* srcv, const void* dstv,
                                              const float* norm, long e0,
                                              int s64, int d64, int tid) {
    int row = tid >> 1, half = tid & 1;
    long e = e0 + row;
    long sidx = s64 ? (long)((const long long*)srcv)[e]
                    : (long)((const int*)srcv)[e];
    const char* srow = (const char*)g_featH + sidx * 256 + half * 128;
    unsigned daddr = smem_u32(Abuf + row * RSTRB + half * 128);
    #pragma unroll
    for (int i = 0; i < 8; i++)
        asm volatile("cp.async.cg.shared.global [%0], [%1], 16;" ::
                     "r"(daddr + i * 16), "l"(srow + i * 16));
    if (tid < 128) {
        long ee = e0 + tid;
        dsts[tid] = d64 ? (int)((const long long*)dstv)[ee]
                        : ((const int*)dstv)[ee];
        nrms[tid] = norm[ee];
    }
}

__global__ void __launch_bounds__(256, 2)
edge_mma_kernel(const void* __restrict__ srcv,
                const void* __restrict__ dstv,
                const float* __restrict__ norm,
                float* __restrict__ out, int section) {
    char* smem = smem_c;
    char* Ws = smem;                         // 128 rows x 272 B
    char* A0 = smem + 34816;
    char* A1 = smem + 69632;
    int*   dst_s = (int*)(smem + 104448);    // [2][128]
    float* nrm_s = (float*)(smem + 105472);  // [2][128]

    int tid = threadIdx.x, warp = tid >> 5, lane = tid & 31;
    long eBase = (long)blockIdx.x * 1024;
    int rel = (int)(eBase / section);

    // Prologue: W^T fp16 (cp.async) + gather tile0 -> buf0, one commit group.
    {
        const char* Wg = (const char*)(g_WH + (size_t)rel * 16384);
        int row = tid >> 1, half = tid & 1;
        unsigned daddr = smem_u32(Ws + row * RSTRB + half * 128);
        const char* srow = Wg + row * 256 + half * 128;
        #pragma unroll
        for (int i = 0; i < 8; i++)
            asm volatile("cp.async.cg.shared.global [%0], [%1], 16;" ::
                         "r"(daddr + i * 16), "l"(srow + i * 16));
    }
    const int s64 = g_src64, d64 = g_dst64;
    gather_tile_h(A0, dst_s, nrm_s, srcv, dstv, norm, eBase, s64, d64, tid);
    CP_COMMIT();

    const int gid = lane >> 2, ctg = lane & 3;
    const int wm = warp & 3, wn = warp >> 2;
    char* Ab[2] = {A0, A1};
    unsigned wsAddr = smem_u32(Ws);

    #pragma unroll 1
    for (int t = 0; t < 8; t++) {
        int b = t & 1;
        __syncthreads();   // epilogue reads of Ab[b^1]-region done; buf reuse safe
        if (t < 7) {
            gather_tile_h(Ab[b ^ 1], dst_s + (b ^ 1) * 128,
                          nrm_s + (b ^ 1) * 128, srcv, dstv, norm,
                          eBase + (long)(t + 1) * 128, s64, d64, tid);
            CP_COMMIT();
            CP_WAIT(1);    // buf b's group complete
        } else {
            CP_WAIT(0);
        }
        __syncthreads();   // all threads' gathers for buf b visible

        float acc[2][8][4];
        #pragma unroll
        for (int mb = 0; mb < 2; mb++)
            #pragma unroll
            for (int nt = 0; nt < 8; nt++)
                #pragma unroll
                for (int q = 0; q < 4; q++) acc[mb][nt][q] = 0.0f;

        mma_tile_h(smem_u32(Ab[b]), wsAddr, warp, lane, acc);

        // Epilogue: norm-scale in regs, stage 64 rows at a time into the
        // consumed A buffer (f32, stride WBSTR), then each warp flushes whole
        // 512B output rows with one float4 atomicAdd warp instruction
        // (32 contiguous lanes = 4 wavefronts/row instead of ~32).
        {
            float* WB = (float*)Ab[b];
            const int* mydst = dst_s + b * 128;
            const float* mynrm = nrm_s + b * 128;
            #pragma unroll
            for (int pass = 0; pass < 2; pass++) {
                __syncthreads();   // pass0: LDSM reads of Ab[b] done; pass1: flush reads done
                if ((wm >> 1) == pass) {
                    int rbase = (wm & 1) * 32;
                    #pragma unroll
                    for (int mb = 0; mb < 2; mb++) {
                        int rA = rbase + mb * 16 + gid;
                        int rB = rA + 8;
                        float nvA = mynrm[pass * 64 + rA];
                        float nvB = mynrm[pass * 64 + rB];
                        #pragma unroll
                        for (int nt = 0; nt < 8; nt++) {
                            int c = wn * 64 + nt * 8 + 2 * ctg;
                            *(float2*)&WB[rA * WBSTR + c] =
                                make_float2(acc[mb][nt][0] * nvA,
                                            acc[mb][nt][1] * nvA);
                            *(float2*)&WB[rB * WBSTR + c] =
                                make_float2(acc[mb][nt][2] * nvB,
                                            acc[mb][nt][3] * nvB);
                        }
                    }
                }
                __syncthreads();
                #pragma unroll
                for (int j = 0; j < 8; j++) {
                    int lr = warp * 8 + j;
                    long dn = mydst[pass * 64 + lr];
                    float4 v = *(float4*)&WB[lr * WBSTR + lane * 4];
                    atomicAdd((float4*)(out + dn * OUT_F + lane * 4), v);
                }
            }
        }
    }
}

// ---------------------------------------------------------------------------
// K3: relu in place
// ---------------------------------------------------------------------------
__global__ void relu_kernel(float* __restrict__ out, int n4) {
    int i = blockIdx.x * blockDim.x + threadIdx.x;
    if (i < n4) {
        float4 v = ((float4*)out)[i];
        v.x = fmaxf(v.x, 0.f);
        v.y = fmaxf(v.y, 0.f);
        v.z = fmaxf(v.z, 0.f);
        v.w = fmaxf(v.w, 0.f);
        ((float4*)out)[i] = v;
    }
}

// ---------------------------------------------------------------------------
extern "C" void kernel_launch(void* const* d_in, const int* in_sizes, int n_in,
                              void* d_out, int out_size) {
    const float* feat        = (const float*)d_in[0];
    const float* weight      = (const float*)d_in[1];
    const float* w_comp      = (const float*)d_in[2];
    const float* h_bias      = (const float*)d_in[3];
    const float* loop_weight = (const float*)d_in[4];
    const float* norm        = (const float*)d_in[5];
    const void*  src         = d_in[6];
    const void*  dst         = d_in[7];

    const int E       = in_sizes[5];
    const int n_nodes = in_sizes[0] / IN_F;
    const int section = E / NUM_RELS;

    float* out = (float*)d_out;

    cudaFuncSetAttribute(selfloop_mma_kernel,
                         cudaFuncAttributeMaxDynamicSharedMemorySize, SELF_SMEM_BYTES);
    cudaFuncSetAttribute(edge_mma_kernel,
                         cudaFuncAttributeMaxDynamicSharedMemorySize, EDGE_SMEM_BYTES);

    // K0: basis composition (W^T fp16) + index detect
    basis_kernel<<<(NUM_RELS * OUT_F * (IN_F / 2) + 255) / 256, 256>>>(weight, w_comp, src, dst);

    // K0b: feat -> fp16
    int n4 = n_nodes * (IN_F / 4);
    half_feat_kernel<<<(n4 + 255) / 256, 256>>>(feat, n4);

    // K1: self-loop (initializes out)
    selfloop_mma_kernel<<<(n_nodes + 127) / 128, 256, SELF_SMEM_BYTES>>>(loop_weight, h_bias, out, n_nodes);

    // K2: edge grouped GEMM (fp16 + ldmatrix) + warp-coherent row atomics
    edge_mma_kernel<<<E / 1024, 256, EDGE_SMEM_BYTES>>>(src, dst, norm, out, section);

    // K3: relu
    relu_kernel<<<(n_nodes * (OUT_F / 4) + 255) / 256, 256>>>(out, n_nodes * (OUT_F / 4));
}

// round 17
// speedup vs baseline: 1.9498x; 1.0292x over previous
#include <cuda_runtime.h>
#include <cuda_fp16.h>
#include <stdint.h>

// Problem constants (fixed by the dataset)
#define NUM_RELS   64
#define NUM_BASES  16
#define IN_F       128
#define OUT_F      128
#define N_CAP      100352          // >= n_nodes (100000)

#define RSTRB 272                  // fp16 tile row stride in bytes (256 data + 16 pad)
#define RSTRH 136

// Scratch (static device globals; no allocations). 65 relations: [64] = loop_weight.
__device__ __half g_featH[(size_t)N_CAP * IN_F];
__device__ __half g_WH[(NUM_RELS + 1) * OUT_F * IN_F];  // W^T fp16, [r][o][k]
__device__ int g_src64;
__device__ int g_dst64;

// ---------------------------------------------------------------------------
// helpers
// ---------------------------------------------------------------------------
__device__ __forceinline__ void mma16(float d[4], unsigned a0, unsigned a1,
                                      unsigned a2, unsigned a3,
                                      unsigned b0, unsigned b1) {
    asm("mma.sync.aligned.m16n8k16.row.col.f32.f16.f16.f32 "
        "{%0,%1,%2,%3},{%4,%5,%6,%7},{%8,%9},{%0,%1,%2,%3};"
        : "+f"(d[0]), "+f"(d[1]), "+f"(d[2]), "+f"(d[3])
        : "r"(a0), "r"(a1), "r"(a2), "r"(a3), "r"(b0), "r"(b1));
}

#define LDSM_X4(r0, r1, r2, r3, addr) \
    asm volatile("ldmatrix.sync.aligned.m8n8.x4.shared.b16 {%0,%1,%2,%3}, [%4];" \
        : "=r"(r0), "=r"(r1), "=r"(r2), "=r"(r3) : "r"(addr))

#define CP16(dst, src) \
    asm volatile("cp.async.cg.shared.global [%0], [%1], 16;" :: "r"(dst), "l"(src))
#define CP_COMMIT() asm volatile("cp.async.commit_group;" ::: "memory")
#define CP_WAIT(N)  asm volatile("cp.async.wait_group %0;" :: "n"(N) : "memory")

extern __shared__ char smem_c[];

__device__ __forceinline__ unsigned smem_u32(const void* p) {
    return (unsigned)__cvta_generic_to_shared(p);
}

// fp16 warp-tile mainloop via ldmatrix: 32x64 per warp, K=128 in 8 k16 slices.
__device__ __forceinline__ void mma_tile_h(unsigned aBase, unsigned bBase,
                                           int warp, int lane, float acc[2][8][4]) {
    const int wm = warp & 3, wn = warp >> 2;
    unsigned aAddr = aBase + (unsigned)((wm * 32 + (lane & 15)) * RSTRB + (lane >> 4) * 16);
    unsigned bAddr = bBase + (unsigned)((wn * 64 + ((lane >> 4) << 3) + (lane & 7)) * RSTRB
                                        + (((lane >> 3) & 1) << 4));
    #pragma unroll
    for (int ks = 0; ks < 8; ks++) {
        unsigned a[2][4], b[4][4];
        #pragma unroll
        for (int mb = 0; mb < 2; mb++)
            LDSM_X4(a[mb][0], a[mb][1], a[mb][2], a[mb][3],
                    aAddr + mb * 16 * RSTRB + ks * 32);
        #pragma unroll
        for (int np = 0; np < 4; np++)
            LDSM_X4(b[np][0], b[np][1], b[np][2], b[np][3],
                    bAddr + np * 16 * RSTRB + ks * 32);
        #pragma unroll
        for (int mb = 0; mb < 2; mb++) {
            #pragma unroll
            for (int np = 0; np < 4; np++) {
                mma16(acc[mb][2 * np + 0], a[mb][0], a[mb][1], a[mb][2], a[mb][3],
                      b[np][0], b[np][1]);
                mma16(acc[mb][2 * np + 1], a[mb][0], a[mb][1], a[mb][2], a[mb][3],
                      b[np][2], b[np][3]);
            }
        }
    }
}

// ---------------------------------------------------------------------------
// K0: basis composition -> W^T fp16 [r][o][k]  (+ idx-width detect)
// ---------------------------------------------------------------------------
__global__ void basis_kernel(const float* __restrict__ weight,
                             const float* __restrict__ w_comp,
                             const void* __restrict__ srcv,
                             const void* __restrict__ dstv) {
    if (blockIdx.x == 0 && threadIdx.x == 0) {
        const unsigned* s = (const unsigned*)srcv;
        const unsigned* d = (const unsigned*)dstv;
        int s64 = 1, d64 = 1;
        #pragma unroll
        for (int i = 1; i < 32; i += 2) {
            if (s[i] != 0u) s64 = 0;
            if (d[i] != 0u) d64 = 0;
        }
        g_src64 = s64;
        g_dst64 = d64;
    }
    int gid = blockIdx.x * blockDim.x + threadIdx.x;
    if (gid >= NUM_RELS * OUT_F * (IN_F / 2)) return;
    int r   = gid >> 13;
    int rem = gid & 8191;
    int o   = rem >> 6;
    int k   = (rem & 63) * 2;
    float a0 = 0.f, a1 = 0.f;
    #pragma unroll
    for (int b = 0; b < NUM_BASES; b++) {
        float c = __ldg(&w_comp[r * NUM_BASES + b]);
        a0 = fmaf(c, __ldg(&weight[(b << 14) + k * OUT_F + o]), a0);
        a1 = fmaf(c, __ldg(&weight[(b << 14) + (k + 1) * OUT_F + o]), a1);
    }
    size_t idx = (size_t)r * 16384 + o * 128 + k;
    *(__half2*)&g_WH[idx] = __floats2half2_rn(a0, a1);
}

// K0c: loop_weight -> g_WH[64] (transposed [o][k])
__global__ void lw_fill_kernel(const float* __restrict__ lw) {
    int i = blockIdx.x * blockDim.x + threadIdx.x;
    if (i < 16384) {
        int o = i >> 7, k = i & 127;
        g_WH[(size_t)NUM_RELS * 16384 + o * 128 + k] = __float2half_rn(__ldg(&lw[k * 128 + o]));
    }
}

// K0b: feat -> fp16
__global__ void half_feat_kernel(const float* __restrict__ feat, int n4) {
    int i = blockIdx.x * blockDim.x + threadIdx.x;
    if (i >= n4) return;
    float4 v = ((const float4*)feat)[i];
    __half2* hp = (__half2*)g_featH;
    hp[i * 2 + 0] = __floats2half2_rn(v.x, v.y);
    hp[i * 2 + 1] = __floats2half2_rn(v.z, v.w);
}

// K1: out[n][:] = bias
__global__ void bias_init_kernel(float* __restrict__ out,
                                 const float* __restrict__ bias, int n4) {
    int i = blockIdx.x * blockDim.x + threadIdx.x;
    if (i < n4)
        ((float4*)out)[i] = __ldg((const float4*)bias + (i & 31));
}

// ---------------------------------------------------------------------------
// K2: unified grouped GEMM (edges rel 0..63 + selfloop as rel 64), 2 CTAs/SM.
// Block = 1024 rows, 8 tiles of 128. Pipelines: data 1 tile ahead, indices
// (src/dst/norm, contiguous -> cp.async) staged 2 tiles ahead in a 4-ring.
// SMEM: Ws 0..34815 | A0 34816 | A1 69632 | idx ring 104448..114687
// ---------------------------------------------------------------------------
#define SM_IDX  104448
#define IDXS_B  2560               // per stage: src 1024 | dst 1024 | norm 512
#define EDGE_SMEM_BYTES 114688
#define WBSTR 132

__device__ __forceinline__ void fetch_idx(char* smem, int st,
                                          const char* srcv, const char* dstv,
                                          const char* normv, long e0,
                                          int s64, int d64, int tid) {
    char* base = smem + SM_IDX + st * IDXS_B;
    int szS = s64 ? 8 : 4, szD = d64 ? 8 : 4;
    int nS = (128 * szS) >> 4, nD = (128 * szD) >> 4;
    if (tid < nS)
        CP16(smem_u32(base + tid * 16), srcv + e0 * szS + tid * 16);
    else if (tid >= 64 && tid < 64 + nD)
        CP16(smem_u32(base + 1024 + (tid - 64) * 16), dstv + e0 * szD + (tid - 64) * 16);
    else if (tid >= 128 && tid < 160)
        CP16(smem_u32(base + 2048 + (tid - 128) * 16), normv + e0 * 4 + (tid - 128) * 16);
}

__device__ __forceinline__ void gather_data(char* smem, char* Abuf, int st,
                                            int selfm, long e0, int n_nodes,
                                            int s64, int tid) {
    int row = tid >> 1, half = tid & 1;
    long sidx;
    if (selfm) {
        sidx = e0 + row;
        if (sidx >= n_nodes) sidx = n_nodes - 1;
    } else {
        const char* base = smem + SM_IDX + st * IDXS_B;
        sidx = s64 ? (long)((const long long*)base)[row]
                   : (long)((const int*)base)[row];
    }
    const char* srow = (const char*)g_featH + sidx * 256 + half * 128;
    unsigned daddr = smem_u32(Abuf + row * RSTRB + half * 128);
    #pragma unroll
    for (int i = 0; i < 8; i++)
        CP16(daddr + i * 16, srow + i * 16);
}

__global__ void __launch_bounds__(256, 2)
edge_mma_kernel(const void* __restrict__ srcv,
                const void* __restrict__ dstv,
                const float* __restrict__ norm,
                float* __restrict__ out, int section,
                int n_nodes, int nCTAe) {
    char* smem = smem_c;
    char* Ws = smem;
    char* A0 = smem + 34816;
    char* A1 = smem + 69632;

    int tid = threadIdx.x, warp = tid >> 5, lane = tid & 31;
    const int selfm = (int)blockIdx.x >= nCTAe;
    long eBase;
    int rel;
    if (selfm) {
        eBase = (long)((int)blockIdx.x - nCTAe) * 1024;
        rel = NUM_RELS;
    } else {
        eBase = (long)blockIdx.x * 1024;
        rel = (int)(eBase / section);
    }
    const int s64 = g_src64, d64 = g_dst64;
    const char* srcc = (const char*)srcv;
    const char* dstc = (const char*)dstv;
    const char* nrmc = (const char*)norm;

    // Prologue group: W + idx(0) + idx(1)
    {
        const char* Wg = (const char*)(g_WH + (size_t)rel * 16384);
        int row = tid >> 1, half = tid & 1;
        unsigned daddr = smem_u32(Ws + row * RSTRB + half * 128);
        const char* srow = Wg + row * 256 + half * 128;
        #pragma unroll
        for (int i = 0; i < 8; i++)
            CP16(daddr + i * 16, srow + i * 16);
    }
    if (!selfm) {
        fetch_idx(smem, 0, srcc, dstc, nrmc, eBase, s64, d64, tid);
        fetch_idx(smem, 1, srcc, dstc, nrmc, eBase + 128, s64, d64, tid);
    }
    CP_COMMIT();
    CP_WAIT(0);
    __syncthreads();

    // G[0]: gather(0) + idx(2)
    gather_data(smem, A0, 0, selfm, eBase, n_nodes, s64, tid);
    if (!selfm) fetch_idx(smem, 2, srcc, dstc, nrmc, eBase + 256, s64, d64, tid);
    CP_COMMIT();

    char* Ab[2] = {A0, A1};
    unsigned wsAddr = smem_u32(Ws);
    const int gid = lane >> 2, ctg = lane & 3;
    const int wm = warp & 3, wn = warp >> 2;

    #pragma unroll 1
    for (int t = 0; t < 8; t++) {
        int b = t & 1;
        __syncthreads();   // epilogue reads of Ab[b^1] done; idx(t+1) visible
        if (t < 7) {
            gather_data(smem, Ab[b ^ 1], (t + 1) & 3, selfm,
                        eBase + (long)(t + 1) * 128, n_nodes, s64, tid);
            if (!selfm && t + 3 < 8)
                fetch_idx(smem, (t + 3) & 3, srcc, dstc, nrmc,
                          eBase + (long)(t + 3) * 128, s64, d64, tid);
            CP_COMMIT();
            CP_WAIT(1);    // tile t's data group complete
        } else {
            CP_WAIT(0);
        }
        __syncthreads();

        float acc[2][8][4];
        #pragma unroll
        for (int mb = 0; mb < 2; mb++)
            #pragma unroll
            for (int nt = 0; nt < 8; nt++)
                #pragma unroll
                for (int q = 0; q < 4; q++) acc[mb][nt][q] = 0.0f;

        mma_tile_h(smem_u32(Ab[b]), wsAddr, warp, lane, acc);

        // Epilogue: norm-scale -> smem WB (consumed A buffer, 64 rows/pass) ->
        // warp-coherent whole-row float4 atomics.
        {
            float* WB = (float*)Ab[b];
            const char* ibase = smem + SM_IDX + (t & 3) * IDXS_B;
            const float* nrm_st = (const float*)(ibase + 2048);
            long rowBase = eBase + (long)t * 128;
            #pragma unroll
            for (int pass = 0; pass < 2; pass++) {
                __syncthreads();
                if ((wm >> 1) == pass) {
                    int rbase = (wm & 1) * 32;
                    #pragma unroll
                    for (int mb = 0; mb < 2; mb++) {
                        int rA = rbase + mb * 16 + gid;
                        int rB = rA + 8;
                        float nvA, nvB;
                        if (selfm) {
                            nvA = (rowBase + pass * 64 + rA < n_nodes) ? 1.f : 0.f;
                            nvB = (rowBase + pass * 64 + rB < n_nodes) ? 1.f : 0.f;
                        } else {
                            nvA = nrm_st[pass * 64 + rA];
                            nvB = nrm_st[pass * 64 + rB];
                        }
                        #pragma unroll
                        for (int nt = 0; nt < 8; nt++) {
                            int c = wn * 64 + nt * 8 + 2 * ctg;
                            *(float2*)&WB[rA * WBSTR + c] =
                                make_float2(acc[mb][nt][0] * nvA,
                                            acc[mb][nt][1] * nvA);
                            *(float2*)&WB[rB * WBSTR + c] =
                                make_float2(acc[mb][nt][2] * nvB,
                                            acc[mb][nt][3] * nvB);
                        }
                    }
                }
                __syncthreads();
                #pragma unroll
                for (int j = 0; j < 8; j++) {
                    int lr = warp * 8 + j;
                    long dn;
                    if (selfm) {
                        dn = rowBase + pass * 64 + lr;
                        if (dn >= n_nodes) dn = n_nodes - 1;
                    } else {
                        dn = d64 ? (long)((const long long*)(ibase + 1024))[pass * 64 + lr]
                                 : (long)((const int*)(ibase + 1024))[pass * 64 + lr];
                    }
                    float4 v = *(float4*)&WB[lr * WBSTR + lane * 4];
                    atomicAdd((float4*)(out + dn * OUT_F + lane * 4), v);
                }
            }
        }
    }
}

// ---------------------------------------------------------------------------
// K3: relu in place
// ---------------------------------------------------------------------------
__global__ void relu_kernel(float* __restrict__ out, int n4) {
    int i = blockIdx.x * blockDim.x + threadIdx.x;
    if (i < n4) {
        float4 v = ((float4*)out)[i];
        v.x = fmaxf(v.x, 0.f);
        v.y = fmaxf(v.y, 0.f);
        v.z = fmaxf(v.z, 0.f);
        v.w = fmaxf(v.w, 0.f);
        ((float4*)out)[i] = v;
    }
}

// ---------------------------------------------------------------------------
extern "C" void kernel_launch(void* const* d_in, const int* in_sizes, int n_in,
                              void* d_out, int out_size) {
    const float* feat        = (const float*)d_in[0];
    const float* weight      = (const float*)d_in[1];
    const float* w_comp      = (const float*)d_in[2];
    const float* h_bias      = (const float*)d_in[3];
    const float* loop_weight = (const float*)d_in[4];
    const float* norm        = (const float*)d_in[5];
    const void*  src         = d_in[6];
    const void*  dst         = d_in[7];

    const int E       = in_sizes[5];
    const int n_nodes = in_sizes[0] / IN_F;
    const int section = E / NUM_RELS;

    float* out = (float*)d_out;

    cudaFuncSetAttribute(edge_mma_kernel,
                         cudaFuncAttributeMaxDynamicSharedMemorySize, EDGE_SMEM_BYTES);

    // K0: basis composition + index detect; loop_weight -> rel 64; feat -> fp16
    basis_kernel<<<(NUM_RELS * OUT_F * (IN_F / 2) + 255) / 256, 256>>>(weight, w_comp, src, dst);
    lw_fill_kernel<<<(16384 + 255) / 256, 256>>>(loop_weight);
    int n4 = n_nodes * (IN_F / 4);
    half_feat_kernel<<<(n4 + 255) / 256, 256>>>(feat, n4);

    // K1: out = bias
    bias_init_kernel<<<(n4 + 255) / 256, 256>>>(out, h_bias, n4);

    // K2: unified grouped GEMM (edges + selfloop) + scatter
    int nCTAe = E / 1024;
    int nCTAs = (n_nodes + 1023) / 1024;
    edge_mma_kernel<<<nCTAe + nCTAs, 256, EDGE_SMEM_BYTES>>>(
        src, dst, norm, out, section, n_nodes, nCTAe);

    // K3: relu
    relu_kernel<<<(n4 + 255) / 256, 256>>>(out, n4);
}